// round 16
// baseline (speedup 1.0000x reference)
#include <cuda_runtime.h>
#include <cuda_bf16.h>
#include <math.h>
#include <stdint.h>

// ---------------- problem constants ----------------
#define NPSD  256
#define SINT  32
#define KPAD  960          // A width: [mid 256][dist 64][head 256][tail 256][rel 32][hfeat 32][tfeat 32][pad 32]
#define NCH   15           // 960/64 chunks for W1 gemm
#define PCH   5            // 320/64 chunks for pred gemm (mid+dist)
#define BMAX  16384

// ---------------- global scratch ----------------
__device__ __align__(16) __nv_bfloat16 g_hi[BMAX * KPAD];
__device__ __align__(16) __nv_bfloat16 g_lo[BMAX * KPAD];
__device__ __align__(16) __nv_bfloat16 Bp1h[NCH * 64 * 64];
__device__ __align__(16) __nv_bfloat16 Bp1l[NCH * 64 * 64];
__device__ __align__(16) __nv_bfloat16 Bp2h[PCH * 64 * 64];
__device__ __align__(16) __nv_bfloat16 Bp2l[PCH * 64 * 64];

// ---------------- helpers ----------------
__device__ __forceinline__ uint32_t s2u(const void* p) {
    uint32_t a;
    asm("{ .reg .u64 t; cvta.to.shared.u64 t, %1; cvt.u32.u64 %0, t; }" : "=r"(a) : "l"(p));
    return a;
}
#define SMEM_SW128(off) ((off) ^ (((off) >> 3) & 0x70))

#define LDSM4(r, addr) \
    asm volatile("ldmatrix.sync.aligned.m8n8.x4.shared.b16 {%0,%1,%2,%3}, [%4];" \
        : "=r"((r)[0]), "=r"((r)[1]), "=r"((r)[2]), "=r"((r)[3]) : "r"(addr))

#define MMA16816(acc, a, bb0, bb1) \
    asm volatile("mma.sync.aligned.m16n8k16.row.col.f32.bf16.bf16.f32 " \
        "{%0,%1,%2,%3}, {%4,%5,%6,%7}, {%8,%9}, {%0,%1,%2,%3};" \
        : "+f"((acc)[0]), "+f"((acc)[1]), "+f"((acc)[2]), "+f"((acc)[3]) \
        : "r"((a)[0]), "r"((a)[1]), "r"((a)[2]), "r"((a)[3]), "r"(bb0), "r"(bb1))

__device__ __forceinline__ void bsplit(float v, __nv_bfloat16& h, __nv_bfloat16& l) {
    h = __float2bfloat16(v);
    l = __float2bfloat16(v - __bfloat162float(h));
}

// ================= prep: split+permute weights into K-chunked bf16 tiles =================
__global__ void gcw_prep(const float* __restrict__ W1,
                         const float* __restrict__ headW,
                         const float* __restrict__ tailW)
{
    int i = blockIdx.x * 256 + threadIdx.x;
    if (i < NCH * 4096) {
        int c = i >> 12, j = (i >> 6) & 63, kk = i & 63;
        int kg = c * 64 + kk;
        int r = (kg < 256) ? 544 + kg          // mid
              : (kg < 320) ? -1                // dist (not in W1)
              : (kg < 864) ? kg - 320          // head, tail, rel
              : (kg < 928) ? kg - 64 : -1;     // hfeat, tfeat ; pad
        float v = (r < 0) ? 0.f : W1[r * 64 + j];
        bsplit(v, Bp1h[i], Bp1l[i]);
    } else if (i < (NCH + PCH) * 4096) {
        int u = i - NCH * 4096;
        int kg = (u >> 12) * 64 + (u & 63);
        int j = (u >> 6) & 63;
        float v = (j < 32) ? headW[kg * 32 + j] : tailW[kg * 32 + (j - 32)];
        bsplit(v, Bp2h[u], Bp2l[u]);
    }
}

// ================= assemble: gather -> A planes (bf16 hi/lo) =================
#define A_LPB 4
__global__ void __launch_bounds__(256) gcw_assemble(
    const float* __restrict__ flat, const float* __restrict__ feat,
    const int* __restrict__ head_idx, const int* __restrict__ rel_idx,
    const int* __restrict__ tail_idx, const int* __restrict__ dist_idx,
    const int* __restrict__ inter, const float* __restrict__ rel_emb,
    const float* __restrict__ dist_emb, float* __restrict__ out, int B)
{
    __shared__ int2 spack[A_LPB * SINT];
    __shared__ int shead[A_LPB], stail[A_LPB], srel[A_LPB], sdi[A_LPB];
    const int t  = threadIdx.x;
    const int b0 = blockIdx.x * A_LPB;

    if (t < A_LPB) {
        int b = min(b0 + t, B - 1);
        shead[t] = head_idx[b]; stail[t] = tail_idx[b];
        srel[t]  = rel_idx[b];  sdi[t]   = dist_idx[b];
    }
    if (t < A_LPB * SINT) {
        int l = t >> 5;
        int b = min(b0 + l, B - 1);
        int c = inter[(long)b * SINT + (t & 31)];
        unsigned m = __ballot_sync(0xFFFFFFFFu, c != -1);
        float inv = 1.f / (float)max(__popc(m), 1);
        float w = (float)((c > -1) - (c < -1)) * inv;
        spack[t] = make_int2((c < 0 ? -c : c) * NPSD, __float_as_int(w));
    }
    __syncthreads();

    const int l  = t >> 6;
    const int c4 = (t & 63) * 4;
    const int br = min(b0 + l, B - 1);
    __nv_bfloat16* gh = g_hi + (long)br * KPAD;
    __nv_bfloat16* gl = g_lo + (long)br * KPAD;

    // head/tail repr -> cols 320/576
    {
        float4 hv = __ldcs((const float4*)&flat[(long)shead[l] * NPSD + c4]);
        float4 tv = __ldcs((const float4*)&flat[(long)stail[l] * NPSD + c4]);
        float vh[4] = {hv.x, hv.y, hv.z, hv.w};
        float vt[4] = {tv.x, tv.y, tv.z, tv.w};
        #pragma unroll
        for (int i = 0; i < 4; i++) {
            bsplit(vh[i], gh[320 + c4 + i], gl[320 + c4 + i]);
            bsplit(vt[i], gh[576 + c4 + i], gl[576 + c4 + i]);
        }
    }
    // mid -> cols 0..256
    {
        const int2* spk = spack + l * SINT;
        const float* fc4 = flat + c4;
        float4 a0 = make_float4(0.f, 0.f, 0.f, 0.f);
        float4 a1 = make_float4(0.f, 0.f, 0.f, 0.f);
        #pragma unroll 4
        for (int s = 0; s < SINT; s += 2) {
            int2 p0 = spk[s];
            int2 p1 = spk[s + 1];
            const float4 v0 = __ldcs((const float4*)(fc4 + p0.x));
            const float4 v1 = __ldcs((const float4*)(fc4 + p1.x));
            float w0 = __int_as_float(p0.y);
            float w1 = __int_as_float(p1.y);
            a0.x = fmaf(v0.x, w0, a0.x); a0.y = fmaf(v0.y, w0, a0.y);
            a0.z = fmaf(v0.z, w0, a0.z); a0.w = fmaf(v0.w, w0, a0.w);
            a1.x = fmaf(v1.x, w1, a1.x); a1.y = fmaf(v1.y, w1, a1.y);
            a1.z = fmaf(v1.z, w1, a1.z); a1.w = fmaf(v1.w, w1, a1.w);
        }
        float r[4] = {a0.x + a1.x, a0.y + a1.y, a0.z + a1.z, a0.w + a1.w};
        #pragma unroll
        for (int i = 0; i < 4; i++) bsplit(r[i], gh[c4 + i], gl[c4 + i]);
    }
    // dist -> cols 256..320
    {
        int j = t & 63;
        float v = dist_emb[sdi[l] * 64 + j];
        bsplit(v, gh[256 + j], gl[256 + j]);
    }
    // rel/hfeat/tfeat/pad -> cols 832..960 (+ emit feats to out)
    long hf = (long)B + 2L * B * 32;
    long tf = (long)B + 3L * B * 32;
    #pragma unroll
    for (int rep = 0; rep < 2; rep++) {
        int u  = rep * 256 + t;
        int ll = u >> 7, jj = u & 127;
        int bb = min(b0 + ll, B - 1);
        float v = 0.f;
        if (jj < 32)       v = rel_emb[srel[ll] * 32 + jj];
        else if (jj < 64)  v = feat[(long)shead[ll] * 32 + (jj - 32)];
        else if (jj < 96)  v = feat[(long)stail[ll] * 32 + (jj - 64)];
        bsplit(v, g_hi[(long)bb * KPAD + 832 + jj], g_lo[(long)bb * KPAD + 832 + jj]);
        if (b0 + ll < B) {
            if (jj >= 32 && jj < 64)      out[hf + (long)(b0 + ll) * 32 + (jj - 32)] = v;
            else if (jj >= 64 && jj < 96) out[tf + (long)(b0 + ll) * 32 + (jj - 64)] = v;
        }
    }
}

// ================= mma: warp-level bf16 HMMA GEMMs + epilogue =================
// smem byte offsets (tile bases 1024-aligned); D1/D2 overlay the tile region after use
#define S_AH   1024
#define S_AL   (S_AH + 16384)
#define S_B1H  (S_AL + 16384)
#define S_B1L  (S_B1H + 8192)
#define S_B2H  (S_B1L + 8192)
#define S_B2L  (S_B2H + 8192)
#define S_TEND (S_B2L + 8192)      // 66560
#define S_D1   1024                 // overlays S_AH.. (32768 bytes)
#define S_D2   (S_D1 + 32768)       // 32768 bytes, ends at 66560
#define S_EPI  S_TEND
#define SMEM_K2 (S_EPI + 2241 * 4)

__global__ void __launch_bounds__(256) gcw_mma(
    const float* __restrict__ W2, const float* __restrict__ b1,
    const float* __restrict__ b2, const float* __restrict__ W3,
    const float* __restrict__ headb, const float* __restrict__ tailb,
    const float* __restrict__ b3, float* __restrict__ out, int B)
{
    extern __shared__ char smem[];
    uint32_t sb = s2u(smem);
    float* sW2T = (float*)(smem + S_EPI);   // [32 j][64 k]
    float* sb1  = sW2T + 2048;
    float* sb2  = sb1 + 64;
    float* sW3  = sb2 + 32;
    float* shb  = sW3 + 32;
    float* stb  = shb + 32;
    float* sb3  = stb + 32;

    const int t = threadIdx.x, wid = t >> 5, lane = t & 31;

    #pragma unroll
    for (int rep = 0; rep < 8; rep++) {
        int u = rep * 256 + t;
        sW2T[u] = W2[(u & 63) * 32 + (u >> 6)];
    }
    if (t < 64) sb1[t] = b1[t];
    if (t < 32) { sb2[t] = b2[t]; sW3[t] = W3[t]; shb[t] = headb[t]; stb[t] = tailb[t]; }
    if (t == 0) sb3[0] = b3[0];

    const int b0 = blockIdx.x * 128;

    // ldmatrix lane address bases (byte offsets within 128B-row SW128 tiles)
    const int mi = lane >> 3, rs = lane & 7;
    const int a_base = (wid * 16 + (mi & 1) * 8 + rs) * 128 + (mi >> 1) * 16;
    const int b_base = ((mi >> 1) * 8 + rs) * 128 + (mi & 1) * 16;

    float acc1[8][4];   // D1 = g_rep @ W1 (N=64)
    float acc2[8][4];   // D2 = md @ [headW|tailW] (N=64)
    #pragma unroll
    for (int n = 0; n < 8; n++)
        #pragma unroll
        for (int i = 0; i < 4; i++) { acc1[n][i] = 0.f; acc2[n][i] = 0.f; }

    #pragma unroll 1
    for (int c = 0; c < NCH; c++) {
        // ---- load A chunk (128 rows x 64 bf16, hi+lo) ----
        #pragma unroll
        for (int r = 0; r < 4; r++) {
            int u = r * 256 + t, row = u >> 3, seg = u & 7;
            long b = min(b0 + row, B - 1);
            long src = b * KPAD + c * 64 + seg * 8;
            uint32_t off = SMEM_SW128((uint32_t)(row * 128 + seg * 16));
            *(uint4*)(smem + S_AH + off) = *(const uint4*)&g_hi[src];
            *(uint4*)(smem + S_AL + off) = *(const uint4*)&g_lo[src];
        }
        // ---- load B chunks (64 rows x 64 bf16 each) ----
        #pragma unroll
        for (int r = 0; r < 2; r++) {
            int u = r * 256 + t, j = u >> 3, seg = u & 7;
            int src = c * 4096 + j * 64 + seg * 8;
            uint32_t off = SMEM_SW128((uint32_t)(j * 128 + seg * 16));
            *(uint4*)(smem + S_B1H + off) = *(const uint4*)&Bp1h[src];
            *(uint4*)(smem + S_B1L + off) = *(const uint4*)&Bp1l[src];
            if (c < PCH) {
                *(uint4*)(smem + S_B2H + off) = *(const uint4*)&Bp2h[src];
                *(uint4*)(smem + S_B2L + off) = *(const uint4*)&Bp2l[src];
            }
        }
        __syncthreads();

        #pragma unroll
        for (int ks = 0; ks < 4; ks++) {
            uint32_t ao = SMEM_SW128((uint32_t)(a_base + ks * 32));
            uint32_t ah[4], al[4];
            LDSM4(ah, sb + S_AH + ao);
            LDSM4(al, sb + S_AL + ao);
            #pragma unroll
            for (int ntp = 0; ntp < 4; ntp++) {
                uint32_t bo = SMEM_SW128((uint32_t)(b_base + ntp * 2048 + ks * 32));
                uint32_t bh[4], bl[4];
                LDSM4(bh, sb + S_B1H + bo);
                LDSM4(bl, sb + S_B1L + bo);
                MMA16816(acc1[2 * ntp],     ah, bh[0], bh[1]);
                MMA16816(acc1[2 * ntp],     ah, bl[0], bl[1]);
                MMA16816(acc1[2 * ntp],     al, bh[0], bh[1]);
                MMA16816(acc1[2 * ntp + 1], ah, bh[2], bh[3]);
                MMA16816(acc1[2 * ntp + 1], ah, bl[2], bl[3]);
                MMA16816(acc1[2 * ntp + 1], al, bh[2], bh[3]);
                if (c < PCH) {
                    uint32_t ph[4], pl[4];
                    LDSM4(ph, sb + S_B2H + bo);
                    LDSM4(pl, sb + S_B2L + bo);
                    MMA16816(acc2[2 * ntp],     ah, ph[0], ph[1]);
                    MMA16816(acc2[2 * ntp],     ah, pl[0], pl[1]);
                    MMA16816(acc2[2 * ntp],     al, ph[0], ph[1]);
                    MMA16816(acc2[2 * ntp + 1], ah, ph[2], ph[3]);
                    MMA16816(acc2[2 * ntp + 1], ah, pl[2], pl[3]);
                    MMA16816(acc2[2 * ntp + 1], al, ph[2], ph[3]);
                }
            }
        }
        __syncthreads();   // tiles consumed; safe to overwrite next iteration
    }

    // ---- write D fragments to smem (overlaying the tile region) ----
    {
        float* D1 = (float*)(smem + S_D1);
        float* D2 = (float*)(smem + S_D2);
        int r = lane >> 2, cg = lane & 3;
        int row0 = wid * 16 + r;
        #pragma unroll
        for (int nt = 0; nt < 8; nt++) {
            int col = nt * 8 + cg * 2;
            *(float2*)&D1[row0 * 64 + col]       = make_float2(acc1[nt][0], acc1[nt][1]);
            *(float2*)&D1[(row0 + 8) * 64 + col] = make_float2(acc1[nt][2], acc1[nt][3]);
            *(float2*)&D2[row0 * 64 + col]       = make_float2(acc2[nt][0], acc2[nt][1]);
            *(float2*)&D2[(row0 + 8) * 64 + col] = make_float2(acc2[nt][2], acc2[nt][3]);
        }
    }
    __syncthreads();

    // ---- epilogue ----
    if (t < 128) {
        // MLP: h1 = relu(D1 + b1); h2 = relu(h1@W2 + b2); out = h2@W3 + b3
        const float* D1 = (const float*)(smem + S_D1);
        int row = t, b = b0 + row;
        float h1[64];
        #pragma unroll
        for (int k = 0; k < 64; k += 4) {
            const float4 d = *(const float4*)&D1[row * 64 + k];
            h1[k]     = fmaxf(d.x + sb1[k], 0.f);
            h1[k + 1] = fmaxf(d.y + sb1[k + 1], 0.f);
            h1[k + 2] = fmaxf(d.z + sb1[k + 2], 0.f);
            h1[k + 3] = fmaxf(d.w + sb1[k + 3], 0.f);
        }
        float o = sb3[0];
        for (int j = 0; j < 32; j++) {
            float a = sb2[j];
            #pragma unroll
            for (int k = 0; k < 64; k += 4) {
                const float4 w = *(const float4*)&sW2T[j * 64 + k];
                a = fmaf(h1[k], w.x, a);
                a = fmaf(h1[k + 1], w.y, a);
                a = fmaf(h1[k + 2], w.z, a);
                a = fmaf(h1[k + 3], w.w, a);
            }
            o = fmaf(fmaxf(a, 0.f), sW3[j], o);
        }
        if (b < B) out[b] = o;
    } else {
        // pred emit: head cols 0..31, tail cols 32..63
        const float* D2 = (const float*)(smem + S_D2);
        int row = t - 128, b = b0 + row;
        if (b < B) {
            long hp = (long)B;
            long tp = (long)B + (long)B * 32;
            #pragma unroll
            for (int j = 0; j < 32; j += 4) {
                float4 dh = *(const float4*)&D2[row * 64 + j];
                float4 dt = *(const float4*)&D2[row * 64 + 32 + j];
                dh.x += shb[j];     dh.y += shb[j + 1];
                dh.z += shb[j + 2]; dh.w += shb[j + 3];
                dt.x += stb[j];     dt.y += stb[j + 1];
                dt.z += stb[j + 2]; dt.w += stb[j + 3];
                *(float4*)&out[hp + (long)b * 32 + j] = dh;
                *(float4*)&out[tp + (long)b * 32 + j] = dt;
            }
        }
    }
}

// ================= launch =================
extern "C" void kernel_launch(void* const* d_in, const int* in_sizes, int n_in,
                              void* d_out, int out_size)
{
    const float* flat     = (const float*)d_in[0];
    const float* feat     = (const float*)d_in[1];
    const int*   head_idx = (const int*)  d_in[2];
    const int*   rel_idx  = (const int*)  d_in[3];
    const int*   tail_idx = (const int*)  d_in[4];
    const int*   dist_idx = (const int*)  d_in[5];
    const int*   inter    = (const int*)  d_in[6];
    const float* rel_emb  = (const float*)d_in[7];
    const float* dist_emb = (const float*)d_in[8];
    const float* headW    = (const float*)d_in[9];
    const float* headb    = (const float*)d_in[10];
    const float* tailW    = (const float*)d_in[11];
    const float* tailb    = (const float*)d_in[12];
    const float* W1       = (const float*)d_in[13];
    const float* b1       = (const float*)d_in[14];
    const float* W2       = (const float*)d_in[15];
    const float* b2       = (const float*)d_in[16];
    const float* W3       = (const float*)d_in[17];
    const float* b3       = (const float*)d_in[18];

    int B = in_sizes[2];

    gcw_prep<<<((NCH + PCH) * 4096 + 255) / 256, 256>>>(W1, headW, tailW);

    gcw_assemble<<<(B + A_LPB - 1) / A_LPB, 256>>>(
        flat, feat, head_idx, rel_idx, tail_idx, dist_idx, inter,
        rel_emb, dist_emb, (float*)d_out, B);

    cudaFuncSetAttribute(gcw_mma, cudaFuncAttributeMaxDynamicSharedMemorySize, SMEM_K2);
    gcw_mma<<<(B + 127) / 128, 256, SMEM_K2>>>(
        W2, b1, b2, W3, headb, tailb, b3, (float*)d_out, B);
}

// round 17
// speedup vs baseline: 1.1607x; 1.1607x over previous
#include <cuda_runtime.h>
#include <cuda_bf16.h>
#include <math.h>
#include <stdint.h>

// ---------------- problem constants ----------------
#define NPSD  256
#define SINT  32
#define KPAD  960          // A width: [mid 256][dist 64][head 256][tail 256][rel 32][hfeat 32][tfeat 32][pad 32]
#define NCH   15           // 960/64 chunks for W1 gemm
#define PCH   5            // 320/64 chunks for pred gemm (mid+dist)
#define BMAX  16384

// ---------------- global scratch ----------------
__device__ __align__(16) __nv_bfloat16 g_hi[BMAX * KPAD];
__device__ __align__(16) __nv_bfloat16 g_lo[BMAX * KPAD];
__device__ __align__(16) __nv_bfloat16 Bp1h[NCH * 64 * 64];
__device__ __align__(16) __nv_bfloat16 Bp1l[NCH * 64 * 64];
__device__ __align__(16) __nv_bfloat16 Bp2h[PCH * 64 * 64];
__device__ __align__(16) __nv_bfloat16 Bp2l[PCH * 64 * 64];

// ---------------- helpers ----------------
__device__ __forceinline__ uint32_t s2u(const void* p) {
    uint32_t a;
    asm("{ .reg .u64 t; cvta.to.shared.u64 t, %1; cvt.u32.u64 %0, t; }" : "=r"(a) : "l"(p));
    return a;
}
#define SMEM_SW128(off) ((off) ^ (((off) >> 3) & 0x70))

#define LDSM4(r, addr) \
    asm volatile("ldmatrix.sync.aligned.m8n8.x4.shared.b16 {%0,%1,%2,%3}, [%4];" \
        : "=r"((r)[0]), "=r"((r)[1]), "=r"((r)[2]), "=r"((r)[3]) : "r"(addr))

#define MMA16816(acc, a, bb0, bb1) \
    asm volatile("mma.sync.aligned.m16n8k16.row.col.f32.bf16.bf16.f32 " \
        "{%0,%1,%2,%3}, {%4,%5,%6,%7}, {%8,%9}, {%0,%1,%2,%3};" \
        : "+f"((acc)[0]), "+f"((acc)[1]), "+f"((acc)[2]), "+f"((acc)[3]) \
        : "r"((a)[0]), "r"((a)[1]), "r"((a)[2]), "r"((a)[3]), "r"(bb0), "r"(bb1))

#define CP16(dst, src) \
    asm volatile("cp.async.cg.shared.global [%0], [%1], 16;" :: "r"(dst), "l"(src))
#define CPCOMMIT() asm volatile("cp.async.commit_group;" ::: "memory")
#define CPWAIT1()  asm volatile("cp.async.wait_group 1;" ::: "memory")
#define CPWAIT0()  asm volatile("cp.async.wait_group 0;" ::: "memory")

__device__ __forceinline__ void bsplit(float v, __nv_bfloat16& h, __nv_bfloat16& l) {
    h = __float2bfloat16(v);
    l = __float2bfloat16(v - __bfloat162float(h));
}

// ================= prep: split+permute weights into K-chunked bf16 tiles =================
__global__ void gcw_prep(const float* __restrict__ W1,
                         const float* __restrict__ headW,
                         const float* __restrict__ tailW)
{
    int i = blockIdx.x * 256 + threadIdx.x;
    if (i < NCH * 4096) {
        int c = i >> 12, j = (i >> 6) & 63, kk = i & 63;
        int kg = c * 64 + kk;
        int r = (kg < 256) ? 544 + kg          // mid
              : (kg < 320) ? -1                // dist (not in W1)
              : (kg < 864) ? kg - 320          // head, tail, rel
              : (kg < 928) ? kg - 64 : -1;     // hfeat, tfeat ; pad
        float v = (r < 0) ? 0.f : W1[r * 64 + j];
        bsplit(v, Bp1h[i], Bp1l[i]);
    } else if (i < (NCH + PCH) * 4096) {
        int u = i - NCH * 4096;
        int kg = (u >> 12) * 64 + (u & 63);
        int j = (u >> 6) & 63;
        float v = (j < 32) ? headW[kg * 32 + j] : tailW[kg * 32 + (j - 32)];
        bsplit(v, Bp2h[u], Bp2l[u]);
    }
}

// ================= assemble: gather -> A planes (bf16 hi/lo) =================
#define A_LPB 4
__global__ void __launch_bounds__(256) gcw_assemble(
    const float* __restrict__ flat, const float* __restrict__ feat,
    const int* __restrict__ head_idx, const int* __restrict__ rel_idx,
    const int* __restrict__ tail_idx, const int* __restrict__ dist_idx,
    const int* __restrict__ inter, const float* __restrict__ rel_emb,
    const float* __restrict__ dist_emb, float* __restrict__ out, int B)
{
    __shared__ int2 spack[A_LPB * SINT];
    __shared__ int shead[A_LPB], stail[A_LPB], srel[A_LPB], sdi[A_LPB];
    const int t  = threadIdx.x;
    const int b0 = blockIdx.x * A_LPB;

    if (t < A_LPB) {
        int b = min(b0 + t, B - 1);
        shead[t] = head_idx[b]; stail[t] = tail_idx[b];
        srel[t]  = rel_idx[b];  sdi[t]   = dist_idx[b];
    }
    if (t < A_LPB * SINT) {
        int l = t >> 5;
        int b = min(b0 + l, B - 1);
        int c = inter[(long)b * SINT + (t & 31)];
        unsigned m = __ballot_sync(0xFFFFFFFFu, c != -1);
        float inv = 1.f / (float)max(__popc(m), 1);
        float w = (float)((c > -1) - (c < -1)) * inv;
        spack[t] = make_int2((c < 0 ? -c : c) * NPSD, __float_as_int(w));
    }
    __syncthreads();

    const int l  = t >> 6;
    const int c4 = (t & 63) * 4;
    const int br = min(b0 + l, B - 1);
    __nv_bfloat16* gh = g_hi + (long)br * KPAD;
    __nv_bfloat16* gl = g_lo + (long)br * KPAD;

    // head/tail repr -> cols 320/576
    {
        float4 hv = __ldcs((const float4*)&flat[(long)shead[l] * NPSD + c4]);
        float4 tv = __ldcs((const float4*)&flat[(long)stail[l] * NPSD + c4]);
        float vh[4] = {hv.x, hv.y, hv.z, hv.w};
        float vt[4] = {tv.x, tv.y, tv.z, tv.w};
        #pragma unroll
        for (int i = 0; i < 4; i++) {
            bsplit(vh[i], gh[320 + c4 + i], gl[320 + c4 + i]);
            bsplit(vt[i], gh[576 + c4 + i], gl[576 + c4 + i]);
        }
    }
    // mid -> cols 0..256
    {
        const int2* spk = spack + l * SINT;
        const float* fc4 = flat + c4;
        float4 a0 = make_float4(0.f, 0.f, 0.f, 0.f);
        float4 a1 = make_float4(0.f, 0.f, 0.f, 0.f);
        #pragma unroll 4
        for (int s = 0; s < SINT; s += 2) {
            int2 p0 = spk[s];
            int2 p1 = spk[s + 1];
            const float4 v0 = __ldcs((const float4*)(fc4 + p0.x));
            const float4 v1 = __ldcs((const float4*)(fc4 + p1.x));
            float w0 = __int_as_float(p0.y);
            float w1 = __int_as_float(p1.y);
            a0.x = fmaf(v0.x, w0, a0.x); a0.y = fmaf(v0.y, w0, a0.y);
            a0.z = fmaf(v0.z, w0, a0.z); a0.w = fmaf(v0.w, w0, a0.w);
            a1.x = fmaf(v1.x, w1, a1.x); a1.y = fmaf(v1.y, w1, a1.y);
            a1.z = fmaf(v1.z, w1, a1.z); a1.w = fmaf(v1.w, w1, a1.w);
        }
        float r[4] = {a0.x + a1.x, a0.y + a1.y, a0.z + a1.z, a0.w + a1.w};
        #pragma unroll
        for (int i = 0; i < 4; i++) bsplit(r[i], gh[c4 + i], gl[c4 + i]);
    }
    // dist -> cols 256..320
    {
        int j = t & 63;
        float v = dist_emb[sdi[l] * 64 + j];
        bsplit(v, gh[256 + j], gl[256 + j]);
    }
    // rel/hfeat/tfeat/pad -> cols 832..960 (+ emit feats to out)
    long hf = (long)B + 2L * B * 32;
    long tf = (long)B + 3L * B * 32;
    #pragma unroll
    for (int rep = 0; rep < 2; rep++) {
        int u  = rep * 256 + t;
        int ll = u >> 7, jj = u & 127;
        int bb = min(b0 + ll, B - 1);
        float v = 0.f;
        if (jj < 32)       v = rel_emb[srel[ll] * 32 + jj];
        else if (jj < 64)  v = feat[(long)shead[ll] * 32 + (jj - 32)];
        else if (jj < 96)  v = feat[(long)stail[ll] * 32 + (jj - 64)];
        bsplit(v, g_hi[(long)bb * KPAD + 832 + jj], g_lo[(long)bb * KPAD + 832 + jj]);
        if (b0 + ll < B) {
            if (jj >= 32 && jj < 64)      out[hf + (long)(b0 + ll) * 32 + (jj - 32)] = v;
            else if (jj >= 64 && jj < 96) out[tf + (long)(b0 + ll) * 32 + (jj - 64)] = v;
        }
    }
}

// ================= mma: cp.async double-buffered bf16 HMMA + epilogue =================
// M = 64 links/block, 128 threads (4 warps), grid = ceil(B/64)
#define MBL   64
#define MTHR  128
#define BUFSZ 49152   // per pipeline buffer: AH 8K, AL 8K, B1H 8K, B1L 8K, B2H 8K, B2L 8K
#define S_AH(p)  ((p) * BUFSZ)
#define S_AL(p)  ((p) * BUFSZ + 8192)
#define S_B1H(p) ((p) * BUFSZ + 16384)
#define S_B1L(p) ((p) * BUFSZ + 24576)
#define S_B2H(p) ((p) * BUFSZ + 32768)
#define S_B2L(p) ((p) * BUFSZ + 40960)
#define S_EPI    (2 * BUFSZ)
#define SMEM_K2  (S_EPI + 2244 * 4)
// D overlays buffer space after MMAs complete
#define S_D1     0
#define S_D2     16384

__device__ __forceinline__ void stage_chunk(uint32_t sb, int c, int p,
                                            int b0, int B, int t)
{
    // A: 64 rows x 64 bf16, hi+lo (512 16B segments per plane)
    #pragma unroll
    for (int r = 0; r < 4; r++) {
        int u = r * MTHR + t, row = u >> 3, seg = u & 7;
        long b = min((long)(b0 + row), (long)(B - 1));
        long src = b * KPAD + c * 64 + seg * 8;
        uint32_t off = SMEM_SW128((uint32_t)(row * 128 + seg * 16));
        CP16(sb + S_AH(p) + off, (const char*)&g_hi[src]);
        CP16(sb + S_AL(p) + off, (const char*)&g_lo[src]);
    }
    // B tiles: 64 rows x 64 bf16 each
    #pragma unroll
    for (int r = 0; r < 4; r++) {
        int u = r * MTHR + t, j = u >> 3, seg = u & 7;
        int src = c * 4096 + j * 64 + seg * 8;
        uint32_t off = SMEM_SW128((uint32_t)(j * 128 + seg * 16));
        CP16(sb + S_B1H(p) + off, (const char*)&Bp1h[src]);
        CP16(sb + S_B1L(p) + off, (const char*)&Bp1l[src]);
        if (c < PCH) {
            CP16(sb + S_B2H(p) + off, (const char*)&Bp2h[src]);
            CP16(sb + S_B2L(p) + off, (const char*)&Bp2l[src]);
        }
    }
}

__global__ void __launch_bounds__(MTHR, 2) gcw_mma(
    const float* __restrict__ W2, const float* __restrict__ b1,
    const float* __restrict__ b2, const float* __restrict__ W3,
    const float* __restrict__ headb, const float* __restrict__ tailb,
    const float* __restrict__ b3, float* __restrict__ out, int B)
{
    extern __shared__ char smem[];
    uint32_t sb = s2u(smem);
    float* sW2T = (float*)(smem + S_EPI);   // [32 j][64 k]
    float* sb1  = sW2T + 2048;
    float* sb2  = sb1 + 64;
    float* sW3  = sb2 + 32;
    float* shb  = sW3 + 32;
    float* stb  = shb + 32;
    float* sb3  = stb + 32;

    const int t = threadIdx.x, wid = t >> 5, lane = t & 31;
    const int b0 = blockIdx.x * MBL;

    #pragma unroll
    for (int rep = 0; rep < 16; rep++) {
        int u = rep * MTHR + t;
        sW2T[u] = W2[(u & 63) * 32 + (u >> 6)];
    }
    if (t < 64) sb1[t] = b1[t];
    if (t < 32) { sb2[t] = b2[t]; sW3[t] = W3[t]; shb[t] = headb[t]; stb[t] = tailb[t]; }
    if (t == 0) sb3[0] = b3[0];

    // ldmatrix lane address bases (byte offsets within 128B-row SW128 tiles)
    const int mi = lane >> 3, rs = lane & 7;
    const int a_base = (wid * 16 + (mi & 1) * 8 + rs) * 128 + (mi >> 1) * 16;
    const int b_base = ((mi >> 1) * 8 + rs) * 128 + (mi & 1) * 16;

    float acc1[8][4];   // D1 = g_rep @ W1 (N=64), rows wid*16..+15
    float acc2[8][4];   // D2 = md @ [headW|tailW]
    #pragma unroll
    for (int n = 0; n < 8; n++)
        #pragma unroll
        for (int i = 0; i < 4; i++) { acc1[n][i] = 0.f; acc2[n][i] = 0.f; }

    stage_chunk(sb, 0, 0, b0, B, t);
    CPCOMMIT();

    #pragma unroll 1
    for (int c = 0; c < NCH; c++) {
        const int p = c & 1;
        if (c + 1 < NCH) {
            stage_chunk(sb, c + 1, p ^ 1, b0, B, t);
            CPCOMMIT();
            CPWAIT1();
        } else {
            CPWAIT0();
        }
        __syncthreads();

        #pragma unroll
        for (int ks = 0; ks < 4; ks++) {
            uint32_t ao = SMEM_SW128((uint32_t)(a_base + ks * 32));
            uint32_t ah[4], al[4];
            LDSM4(ah, sb + S_AH(p) + ao);
            LDSM4(al, sb + S_AL(p) + ao);
            #pragma unroll
            for (int ntp = 0; ntp < 4; ntp++) {
                uint32_t bo = SMEM_SW128((uint32_t)(b_base + ntp * 2048 + ks * 32));
                uint32_t bh[4], bl[4];
                LDSM4(bh, sb + S_B1H(p) + bo);
                LDSM4(bl, sb + S_B1L(p) + bo);
                MMA16816(acc1[2 * ntp],     ah, bh[0], bh[1]);
                MMA16816(acc1[2 * ntp],     ah, bl[0], bl[1]);
                MMA16816(acc1[2 * ntp],     al, bh[0], bh[1]);
                MMA16816(acc1[2 * ntp + 1], ah, bh[2], bh[3]);
                MMA16816(acc1[2 * ntp + 1], ah, bl[2], bl[3]);
                MMA16816(acc1[2 * ntp + 1], al, bh[2], bh[3]);
                if (c < PCH) {
                    uint32_t ph[4], pl[4];
                    LDSM4(ph, sb + S_B2H(p) + bo);
                    LDSM4(pl, sb + S_B2L(p) + bo);
                    MMA16816(acc2[2 * ntp],     ah, ph[0], ph[1]);
                    MMA16816(acc2[2 * ntp],     ah, pl[0], pl[1]);
                    MMA16816(acc2[2 * ntp],     al, ph[0], ph[1]);
                    MMA16816(acc2[2 * ntp + 1], ah, ph[2], ph[3]);
                    MMA16816(acc2[2 * ntp + 1], ah, pl[2], pl[3]);
                    MMA16816(acc2[2 * ntp + 1], al, ph[2], ph[3]);
                }
            }
        }
        __syncthreads();   // buffer p free for restage at c+2
    }

    // ---- write D fragments to smem (overlaying buffer space) ----
    {
        float* D1 = (float*)(smem + S_D1);
        float* D2 = (float*)(smem + S_D2);
        int r = lane >> 2, cg = lane & 3;
        int row0 = wid * 16 + r;
        #pragma unroll
        for (int nt = 0; nt < 8; nt++) {
            int col = nt * 8 + cg * 2;
            *(float2*)&D1[row0 * 64 + col]       = make_float2(acc1[nt][0], acc1[nt][1]);
            *(float2*)&D1[(row0 + 8) * 64 + col] = make_float2(acc1[nt][2], acc1[nt][3]);
            *(float2*)&D2[row0 * 64 + col]       = make_float2(acc2[nt][0], acc2[nt][1]);
            *(float2*)&D2[(row0 + 8) * 64 + col] = make_float2(acc2[nt][2], acc2[nt][3]);
        }
    }
    __syncthreads();

    // ---- epilogue ----
    if (t < 64) {
        // MLP: h1 = relu(D1 + b1); h2 = relu(h1@W2 + b2); out = h2@W3 + b3
        const float* D1 = (const float*)(smem + S_D1);
        int row = t, b = b0 + row;
        float h1[64];
        #pragma unroll
        for (int k = 0; k < 64; k += 4) {
            const float4 d = *(const float4*)&D1[row * 64 + k];
            h1[k]     = fmaxf(d.x + sb1[k], 0.f);
            h1[k + 1] = fmaxf(d.y + sb1[k + 1], 0.f);
            h1[k + 2] = fmaxf(d.z + sb1[k + 2], 0.f);
            h1[k + 3] = fmaxf(d.w + sb1[k + 3], 0.f);
        }
        float o = sb3[0];
        for (int j = 0; j < 32; j++) {
            float a = sb2[j];
            #pragma unroll
            for (int k = 0; k < 64; k += 4) {
                const float4 w = *(const float4*)&sW2T[j * 64 + k];
                a = fmaf(h1[k], w.x, a);
                a = fmaf(h1[k + 1], w.y, a);
                a = fmaf(h1[k + 2], w.z, a);
                a = fmaf(h1[k + 3], w.w, a);
            }
            o = fmaf(fmaxf(a, 0.f), sW3[j], o);
        }
        if (b < B) out[b] = o;
    } else {
        // pred emit: head cols 0..31, tail cols 32..63
        const float* D2 = (const float*)(smem + S_D2);
        int row = t - 64, b = b0 + row;
        if (b < B) {
            long hp = (long)B;
            long tp = (long)B + (long)B * 32;
            #pragma unroll
            for (int j = 0; j < 32; j += 4) {
                float4 dh = *(const float4*)&D2[row * 64 + j];
                float4 dt = *(const float4*)&D2[row * 64 + 32 + j];
                dh.x += shb[j];     dh.y += shb[j + 1];
                dh.z += shb[j + 2]; dh.w += shb[j + 3];
                dt.x += stb[j];     dt.y += stb[j + 1];
                dt.z += stb[j + 2]; dt.w += stb[j + 3];
                *(float4*)&out[hp + (long)b * 32 + j] = dh;
                *(float4*)&out[tp + (long)b * 32 + j] = dt;
            }
        }
    }
}

// ================= launch =================
extern "C" void kernel_launch(void* const* d_in, const int* in_sizes, int n_in,
                              void* d_out, int out_size)
{
    const float* flat     = (const float*)d_in[0];
    const float* feat     = (const float*)d_in[1];
    const int*   head_idx = (const int*)  d_in[2];
    const int*   rel_idx  = (const int*)  d_in[3];
    const int*   tail_idx = (const int*)  d_in[4];
    const int*   dist_idx = (const int*)  d_in[5];
    const int*   inter    = (const int*)  d_in[6];
    const float* rel_emb  = (const float*)d_in[7];
    const float* dist_emb = (const float*)d_in[8];
    const float* headW    = (const float*)d_in[9];
    const float* headb    = (const float*)d_in[10];
    const float* tailW    = (const float*)d_in[11];
    const float* tailb    = (const float*)d_in[12];
    const float* W1       = (const float*)d_in[13];
    const float* b1       = (const float*)d_in[14];
    const float* W2       = (const float*)d_in[15];
    const float* b2       = (const float*)d_in[16];
    const float* W3       = (const float*)d_in[17];
    const float* b3       = (const float*)d_in[18];

    int B = in_sizes[2];

    gcw_prep<<<((NCH + PCH) * 4096 + 255) / 256, 256>>>(W1, headW, tailW);

    gcw_assemble<<<(B + A_LPB - 1) / A_LPB, 256>>>(
        flat, feat, head_idx, rel_idx, tail_idx, dist_idx, inter,
        rel_emb, dist_emb, (float*)d_out, B);

    cudaFuncSetAttribute(gcw_mma, cudaFuncAttributeMaxDynamicSharedMemorySize, SMEM_K2);
    gcw_mma<<<(B + MBL - 1) / MBL, MTHR, SMEM_K2>>>(
        W2, b1, b2, W3, headb, tailb, b3, (float*)d_out, B);
}